// round 1
// baseline (speedup 1.0000x reference)
#include <cuda_runtime.h>

#define T_STEPS 1024
#define NB 8192
#define NP 6

__global__ __launch_bounds__(64, 16)
void hydro_kernel(const float* __restrict__ prcp,
                  const float* __restrict__ temp,
                  const float* __restrict__ pet,
                  const float* __restrict__ sparams,
                  float* __restrict__ out)
{
    const int b = blockIdx.x * blockDim.x + threadIdx.x;
    if (b >= NB) return;

    // ---- denormalize params: sigmoid then affine to bounds ----
    // order: f, Smax, Qmax, Df, Tmax, Tmin
    const float lo[NP] = {0.0f, 100.0f, 10.0f, 0.0f, 0.0f, -3.0f};
    const float hi[NP] = {0.1f, 1500.0f, 50.0f, 5.0f, 3.0f, 0.0f};
    float prm[NP];
#pragma unroll
    for (int i = 0; i < NP; i++) {
        float x = sparams[b * NP + i];
        float s = 1.0f / (1.0f + __expf(-x));   // sigmoid (MUFU.EX2 path)
        prm[i] = lo[i] + (hi[i] - lo[i]) * s;
    }
    const float f    = prm[0];
    const float Smax = prm[1];
    const float Qmax = prm[2];
    const float Df   = prm[3];
    const float Tmax = prm[4];
    const float Tmin = prm[5];

    const float invSmax = 1.0f / Smax;
    const float negf_l2 = -f * 1.4426950408889634f;  // for exp2: exp(-f*x) = 2^(negf_l2*x)

    float snow = 0.0f;
    float soil = 0.0f;

    // prefetched forcings for the current step
    float p  = __ldcs(&prcp[b]);
    float tm = __ldcs(&temp[b]);
    float pe = __ldcs(&pet[b]);

#pragma unroll 4
    for (int t = 0; t < T_STEPS; t++) {
        // prefetch next step's forcings (independent of state -> hides DRAM latency)
        const int tn = (t + 1 < T_STEPS) ? (t + 1) : t;
        const float np  = __ldcs(&prcp[(size_t)tn * NB + b]);
        const float ntm = __ldcs(&temp[(size_t)tn * NB + b]);
        const float npe = __ldcs(&pet [(size_t)tn * NB + b]);

        // ---- hydrofluxes ----
        const float snowfall    = (tm < Tmin) ? p : 0.0f;
        const float rainfall    = p - snowfall;
        const float melt        = fminf(snow, Df * fmaxf(tm - Tmax, 0.0f));
        const float evap        = pe * fminf(soil * invSmax, 1.0f);
        const float baseflow    = Qmax * exp2f(negf_l2 * fmaxf(Smax - soil, 0.0f));
        const float surfaceflow = fmaxf(soil - Smax, 0.0f);

        // ---- state deltas ----
        const float d_snow = snowfall - melt;
        const float d_soil = rainfall + melt - evap - baseflow - surfaceflow;

        // ---- state update with nearzero clamp ----
        snow = fmaxf(snow + d_snow, 1e-6f);
        soil = fmaxf(soil + d_soil, 1e-6f);

        // ---- outputs: [T, 8, B], streaming stores (write-once data) ----
        float* o = out + (size_t)t * (8 * NB) + b;
        __stcs(o + 0 * NB, snowfall);
        __stcs(o + 1 * NB, rainfall);
        __stcs(o + 2 * NB, melt);
        __stcs(o + 3 * NB, evap);
        __stcs(o + 4 * NB, baseflow);
        __stcs(o + 5 * NB, surfaceflow);
        __stcs(o + 6 * NB, d_snow);
        __stcs(o + 7 * NB, d_soil);

        p = np; tm = ntm; pe = npe;
    }
}

extern "C" void kernel_launch(void* const* d_in, const int* in_sizes, int n_in,
                              void* d_out, int out_size)
{
    const float* prcp = (const float*)d_in[0];
    const float* temp = (const float*)d_in[1];
    const float* pet  = (const float*)d_in[2];
    const float* sp   = (const float*)d_in[3];
    float* out = (float*)d_out;

    // 128 blocks x 64 threads = 8192 threads; 2 warps/block -> 2 SMSPs/SM,
    // spread over 128 SMs => 256 SMSPs each holding exactly 1 warp.
    hydro_kernel<<<128, 64>>>(prcp, temp, pet, sp, out);
}

// round 2
// speedup vs baseline: 1.3818x; 1.3818x over previous
#include <cuda_runtime.h>

#define T_STEPS 1024
#define NB 8192
#define NP 6
#define BATCH 8
#define NBATCH (T_STEPS / BATCH)

__global__ __launch_bounds__(32, 32)
void hydro_kernel(const float* __restrict__ prcp,
                  const float* __restrict__ temp,
                  const float* __restrict__ pet,
                  const float* __restrict__ sparams,
                  float* __restrict__ out)
{
    const int b = blockIdx.x * blockDim.x + threadIdx.x;
    if (b >= NB) return;

    // ---- denormalize params: sigmoid then affine to bounds ----
    // order: f, Smax, Qmax, Df, Tmax, Tmin
    const float lo[NP] = {0.0f, 100.0f, 10.0f, 0.0f, 0.0f, -3.0f};
    const float hi[NP] = {0.1f, 1500.0f, 50.0f, 5.0f, 3.0f, 0.0f};
    float prm[NP];
#pragma unroll
    for (int i = 0; i < NP; i++) {
        float x = sparams[b * NP + i];
        float s = 1.0f / (1.0f + __expf(-x));
        prm[i] = lo[i] + (hi[i] - lo[i]) * s;
    }
    const float f    = prm[0];
    const float Smax = prm[1];
    const float Qmax = prm[2];
    const float Df   = prm[3];
    const float Tmax = prm[4];
    const float Tmin = prm[5];

    const float invSmax = 1.0f / Smax;
    const float negf_l2 = -f * 1.4426950408889634f;  // exp(-f*x) = 2^(negf_l2*x)

    float snow = 0.0f;
    float soil = 0.0f;

    const float* pp = prcp + b;
    const float* tp = temp + b;
    const float* ep = pet  + b;
    float*       o  = out  + b;

    // ---- deep prefetch: 8 timesteps (24 loads) in flight ----
    float P[BATCH], TM[BATCH], PE[BATCH];
#pragma unroll
    for (int i = 0; i < BATCH; i++) {
        P[i]  = __ldcs(pp + i * NB);
        TM[i] = __ldcs(tp + i * NB);
        PE[i] = __ldcs(ep + i * NB);
    }
    pp += BATCH * NB; tp += BATCH * NB; ep += BATCH * NB;

    for (int tb = 0; tb < NBATCH; tb++) {
        // prefetch the NEXT batch before computing the current one,
        // so 24 loads overlap ~8 steps of compute + stores
        float Pn[BATCH], TMn[BATCH], PEn[BATCH];
        const bool more = (tb + 1 < NBATCH);
        if (more) {
#pragma unroll
            for (int i = 0; i < BATCH; i++) {
                Pn[i]  = __ldcs(pp + i * NB);
                TMn[i] = __ldcs(tp + i * NB);
                PEn[i] = __ldcs(ep + i * NB);
            }
        }

#pragma unroll
        for (int i = 0; i < BATCH; i++) {
            const float p  = P[i];
            const float tm = TM[i];
            const float pe = PE[i];

            const float snowfall    = (tm < Tmin) ? p : 0.0f;
            const float rainfall    = p - snowfall;
            const float melt        = fminf(snow, Df * fmaxf(tm - Tmax, 0.0f));
            const float evap        = pe * fminf(soil * invSmax, 1.0f);
            const float baseflow    = Qmax * exp2f(negf_l2 * fmaxf(Smax - soil, 0.0f));
            const float surfaceflow = fmaxf(soil - Smax, 0.0f);

            const float d_snow = snowfall - melt;
            const float d_soil = rainfall + melt - evap - baseflow - surfaceflow;

            snow = fmaxf(snow + d_snow, 1e-6f);
            soil = fmaxf(soil + d_soil, 1e-6f);

            // outputs: [T, 8, B] — streaming stores, immediate offsets
            __stcs(o + 0 * NB, snowfall);
            __stcs(o + 1 * NB, rainfall);
            __stcs(o + 2 * NB, melt);
            __stcs(o + 3 * NB, evap);
            __stcs(o + 4 * NB, baseflow);
            __stcs(o + 5 * NB, surfaceflow);
            __stcs(o + 6 * NB, d_snow);
            __stcs(o + 7 * NB, d_soil);
            o += 8 * NB;
        }

        if (more) {
#pragma unroll
            for (int i = 0; i < BATCH; i++) {
                P[i] = Pn[i]; TM[i] = TMn[i]; PE[i] = PEn[i];
            }
        }
        pp += BATCH * NB; tp += BATCH * NB; ep += BATCH * NB;
    }
}

extern "C" void kernel_launch(void* const* d_in, const int* in_sizes, int n_in,
                              void* d_out, int out_size)
{
    const float* prcp = (const float*)d_in[0];
    const float* temp = (const float*)d_in[1];
    const float* pet  = (const float*)d_in[2];
    const float* sp   = (const float*)d_in[3];
    float* out = (float*)d_out;

    // 256 blocks x 32 threads = 8192 threads; 1 warp/block spread over all
    // 148 SMs (most SMs get 2 blocks on different SMSPs) -> per-SM LSU/L1tex
    // traffic is spread as widely as the basin count allows.
    hydro_kernel<<<256, 32>>>(prcp, temp, pet, sp, out);
}

// round 3
// speedup vs baseline: 1.6334x; 1.1820x over previous
#include <cuda_runtime.h>

#define T_STEPS 1024
#define NB 8192
#define NP 6
#define CHUNKS 16
#define CLEN (T_STEPS / CHUNKS)      // 64 steps per chunk
#define BATCH 8
#define NBATCH1 (T_STEPS / BATCH)    // 128 batches in pass 1
#define NBATCH2 (CLEN / BATCH)       // 8 batches per chunk in pass 2

// checkpoint scratch: state at the START of each chunk
__device__ float g_ck_snow[CHUNKS * NB];
__device__ float g_ck_soil[CHUNKS * NB];

struct Params {
    float Qmax, Df, Tmax, Tmin, Smax, invSmax, posf_l2, c0;
};

__device__ __forceinline__ Params load_params(const float* __restrict__ sp, int b)
{
    const float lo[NP] = {0.0f, 100.0f, 10.0f, 0.0f, 0.0f, -3.0f};
    const float hi[NP] = {0.1f, 1500.0f, 50.0f, 5.0f, 3.0f, 0.0f};
    float prm[NP];
#pragma unroll
    for (int i = 0; i < NP; i++) {
        float x = sp[b * NP + i];
        float s = 1.0f / (1.0f + __expf(-x));
        prm[i] = lo[i] + (hi[i] - lo[i]) * s;
    }
    Params q;
    q.Smax = prm[1]; q.Qmax = prm[2]; q.Df = prm[3];
    q.Tmax = prm[4]; q.Tmin = prm[5];
    q.invSmax = 1.0f / prm[1];
    const float negf_l2 = -prm[0] * 1.4426950408889634f;   // -f*log2(e)
    q.posf_l2 = -negf_l2;                                   //  f*log2(e)
    q.c0 = negf_l2 * prm[1];                                // -f*log2(e)*Smax
    return q;
}

// one EXP-HYDRO step; critical chain through soil is FFMA->FMNMX->MUFU->FMUL->FADD->FMNMX
__device__ __forceinline__ void hydro_step(const Params& q,
                                           float p, float tm, float pe,
                                           float& snow, float& soil,
                                           float fx[8])
{
    const float snowfall    = (tm < q.Tmin) ? p : 0.0f;
    const float rainfall    = p - snowfall;
    const float melt        = fminf(snow, q.Df * fmaxf(tm - q.Tmax, 0.0f));
    const float evap        = pe * fminf(soil * q.invSmax, 1.0f);
    // Qmax * exp(-f*max(Smax-soil,0)) == Qmax * 2^min(c0 + posf_l2*soil, 0)
    const float baseflow    = q.Qmax * exp2f(fminf(fmaf(q.posf_l2, soil, q.c0), 0.0f));
    const float surfaceflow = fmaxf(soil - q.Smax, 0.0f);

    const float d_snow = snowfall - melt;
    const float d_soil = rainfall + melt - evap - baseflow - surfaceflow;

    snow = fmaxf(snow + d_snow, 1e-6f);
    soil = fmaxf(soil + d_soil, 1e-6f);

    fx[0] = snowfall; fx[1] = rainfall; fx[2] = melt; fx[3] = evap;
    fx[4] = baseflow; fx[5] = surfaceflow; fx[6] = d_snow; fx[7] = d_soil;
}

// ---------------- pass 1: serial state scan, checkpoints every CLEN steps ----
__global__ void __launch_bounds__(32)
hydro_pass1(const float* __restrict__ prcp,
            const float* __restrict__ temp,
            const float* __restrict__ pet,
            const float* __restrict__ sp)
{
    const int b = blockIdx.x * 32 + threadIdx.x;
    const Params q = load_params(sp, b);

    float snow = 0.0f, soil = 0.0f;
    const float* pp = prcp + b;
    const float* tp = temp + b;
    const float* ep = pet  + b;

    float PA[BATCH], TA[BATCH], EA[BATCH];
    float PB[BATCH], TB[BATCH], EB[BATCH];
    float fx[8];

#pragma unroll
    for (int i = 0; i < BATCH; i++) {
        PA[i] = pp[i * NB]; TA[i] = tp[i * NB]; EA[i] = ep[i * NB];
    }

    for (int tb = 0; tb < NBATCH1; tb += 2) {
        // prefetch batch tb+1 into B while computing A
        {
            const size_t base = (size_t)(tb + 1) * BATCH * NB;
#pragma unroll
            for (int i = 0; i < BATCH; i++) {
                PB[i] = pp[base + i * NB]; TB[i] = tp[base + i * NB]; EB[i] = ep[base + i * NB];
            }
        }
        // chunk boundaries land on even batch indices only (8 batches per chunk)
        if ((tb & (NBATCH2 - 1)) == 0) {
            const int c = tb / NBATCH2;
            g_ck_snow[c * NB + b] = snow;
            g_ck_soil[c * NB + b] = soil;
        }
#pragma unroll
        for (int i = 0; i < BATCH; i++)
            hydro_step(q, PA[i], TA[i], EA[i], snow, soil, fx);

        // prefetch batch tb+2 into A while computing B
        if (tb + 2 < NBATCH1) {
            const size_t base = (size_t)(tb + 2) * BATCH * NB;
#pragma unroll
            for (int i = 0; i < BATCH; i++) {
                PA[i] = pp[base + i * NB]; TA[i] = tp[base + i * NB]; EA[i] = ep[base + i * NB];
            }
        }
#pragma unroll
        for (int i = 0; i < BATCH; i++)
            hydro_step(q, PB[i], TB[i], EB[i], snow, soil, fx);
    }

    // keep fx live so the compiler can't DCE the flux math differently than pass2
    if (b < 0) g_ck_soil[b & 1] = fx[0] + fx[1] + fx[2] + fx[3] + fx[4] + fx[5] + fx[6] + fx[7];
}

// ---------------- pass 2: parallel chunks from checkpoints, store all fluxes --
__global__ void __launch_bounds__(32)
hydro_pass2(const float* __restrict__ prcp,
            const float* __restrict__ temp,
            const float* __restrict__ pet,
            const float* __restrict__ sp,
            float* __restrict__ out)
{
    const int b = blockIdx.x * 32 + threadIdx.x;
    const int c = blockIdx.y;
    const Params q = load_params(sp, b);

    float snow = g_ck_snow[c * NB + b];
    float soil = g_ck_soil[c * NB + b];

    const size_t t0 = (size_t)c * CLEN;
    const float* pp = prcp + t0 * NB + b;
    const float* tp = temp + t0 * NB + b;
    const float* ep = pet  + t0 * NB + b;
    float*       o  = out  + t0 * (8 * NB) + b;

    float PA[BATCH], TA[BATCH], EA[BATCH];
    float PB[BATCH], TB[BATCH], EB[BATCH];
    float fx[8];

#pragma unroll
    for (int i = 0; i < BATCH; i++) {
        PA[i] = pp[i * NB]; TA[i] = tp[i * NB]; EA[i] = ep[i * NB];
    }

    for (int tb = 0; tb < NBATCH2; tb += 2) {
        {
            const size_t base = (size_t)(tb + 1) * BATCH * NB;
#pragma unroll
            for (int i = 0; i < BATCH; i++) {
                PB[i] = pp[base + i * NB]; TB[i] = tp[base + i * NB]; EB[i] = ep[base + i * NB];
            }
        }
#pragma unroll
        for (int i = 0; i < BATCH; i++) {
            hydro_step(q, PA[i], TA[i], EA[i], snow, soil, fx);
            __stcs(o + 0 * NB, fx[0]); __stcs(o + 1 * NB, fx[1]);
            __stcs(o + 2 * NB, fx[2]); __stcs(o + 3 * NB, fx[3]);
            __stcs(o + 4 * NB, fx[4]); __stcs(o + 5 * NB, fx[5]);
            __stcs(o + 6 * NB, fx[6]); __stcs(o + 7 * NB, fx[7]);
            o += 8 * NB;
        }
        if (tb + 2 < NBATCH2) {
            const size_t base = (size_t)(tb + 2) * BATCH * NB;
#pragma unroll
            for (int i = 0; i < BATCH; i++) {
                PA[i] = pp[base + i * NB]; TA[i] = tp[base + i * NB]; EA[i] = ep[base + i * NB];
            }
        }
#pragma unroll
        for (int i = 0; i < BATCH; i++) {
            hydro_step(q, PB[i], TB[i], EB[i], snow, soil, fx);
            __stcs(o + 0 * NB, fx[0]); __stcs(o + 1 * NB, fx[1]);
            __stcs(o + 2 * NB, fx[2]); __stcs(o + 3 * NB, fx[3]);
            __stcs(o + 4 * NB, fx[4]); __stcs(o + 5 * NB, fx[5]);
            __stcs(o + 6 * NB, fx[6]); __stcs(o + 7 * NB, fx[7]);
            o += 8 * NB;
        }
    }
}

extern "C" void kernel_launch(void* const* d_in, const int* in_sizes, int n_in,
                              void* d_out, int out_size)
{
    const float* prcp = (const float*)d_in[0];
    const float* temp = (const float*)d_in[1];
    const float* pet  = (const float*)d_in[2];
    const float* sp   = (const float*)d_in[3];
    float* out = (float*)d_out;

    // pass 1: 256 warps do the serial state scan, writing chunk checkpoints
    hydro_pass1<<<NB / 32, 32>>>(prcp, temp, pet, sp);
    // pass 2: 16 chunks x 256 warp-blocks = 4096 warps, recompute + store fluxes
    dim3 grid2(NB / 32, CHUNKS);
    hydro_pass2<<<grid2, 32>>>(prcp, temp, pet, sp, out);
}

// round 4
// speedup vs baseline: 2.1498x; 1.3162x over previous
#include <cuda_runtime.h>

#define T_STEPS 1024
#define NB 8192
#define NP 6
#define CHUNKS 32
#define CLEN (T_STEPS / CHUNKS)      // 32 steps per chunk
#define B1 8                         // pass-1 register batch
#define NBT1 (T_STEPS / B1)          // 128 batches
#define B2 4                         // pass-2 register batch
#define NBT2 (CLEN / B2)             // 8 batches per chunk

// checkpoint scratch: state at the START of each chunk (2 MB total -> lives in L2)
__device__ float g_ck_snow[CHUNKS * NB];
__device__ float g_ck_soil[CHUNKS * NB];

struct Params {
    float Qmax, Df, Tmax, Tmin, Smax, invSmax, posf_l2, c0;
};

__device__ __forceinline__ Params load_params(const float* __restrict__ sp, int b)
{
    const float lo[NP] = {0.0f, 100.0f, 10.0f, 0.0f, 0.0f, -3.0f};
    const float hi[NP] = {0.1f, 1500.0f, 50.0f, 5.0f, 3.0f, 0.0f};
    float prm[NP];
#pragma unroll
    for (int i = 0; i < NP; i++) {
        float x = sp[b * NP + i];
        float s = 1.0f / (1.0f + __expf(-x));
        prm[i] = lo[i] + (hi[i] - lo[i]) * s;
    }
    Params q;
    q.Smax = prm[1]; q.Qmax = prm[2]; q.Df = prm[3];
    q.Tmax = prm[4]; q.Tmin = prm[5];
    q.invSmax = 1.0f / prm[1];
    const float negf_l2 = -prm[0] * 1.4426950408889634f;   // -f*log2(e)
    q.posf_l2 = -negf_l2;
    q.c0 = negf_l2 * prm[1];                                // -f*log2(e)*Smax
    return q;
}

__device__ __forceinline__ void hydro_step(const Params& q,
                                           float p, float tm, float pe,
                                           float& snow, float& soil,
                                           float fx[8])
{
    const float snowfall    = (tm < q.Tmin) ? p : 0.0f;
    const float rainfall    = p - snowfall;
    const float melt        = fminf(snow, q.Df * fmaxf(tm - q.Tmax, 0.0f));
    const float evap        = pe * fminf(soil * q.invSmax, 1.0f);
    // Qmax * exp(-f*max(Smax-soil,0)) == Qmax * 2^min(c0 + posf_l2*soil, 0)
    const float baseflow    = q.Qmax * exp2f(fminf(fmaf(q.posf_l2, soil, q.c0), 0.0f));
    const float surfaceflow = fmaxf(soil - q.Smax, 0.0f);

    const float d_snow = snowfall - melt;
    const float d_soil = rainfall + melt - evap - baseflow - surfaceflow;

    snow = fmaxf(snow + d_snow, 1e-6f);
    soil = fmaxf(soil + d_soil, 1e-6f);

    fx[0] = snowfall; fx[1] = rainfall; fx[2] = melt; fx[3] = evap;
    fx[4] = baseflow; fx[5] = surfaceflow; fx[6] = d_snow; fx[7] = d_soil;
}

__device__ __forceinline__ void pfL2(const float* p)
{
    asm volatile("prefetch.global.L2 [%0];" :: "l"(p));
}

// ---------------- pass 1: serial state scan with deep L2 prefetch -----------
__global__ void __launch_bounds__(32)
hydro_pass1(const float* __restrict__ prcp,
            const float* __restrict__ temp,
            const float* __restrict__ pet,
            const float* __restrict__ sp)
{
    const int b = blockIdx.x * 32 + threadIdx.x;
    const Params q = load_params(sp, b);

    float snow = 0.0f, soil = 0.0f;
    const float* pp = prcp + b;
    const float* tp = temp + b;
    const float* ep = pet  + b;

    float PA[B1], TA[B1], EA[B1];
    float PB[B1], TB[B1], EB[B1];
    float fx[8];

    // warm up: regs <- batch 0; L2 <- batches 1..3
#pragma unroll
    for (int i = 0; i < B1; i++) {
        PA[i] = pp[i * NB]; TA[i] = tp[i * NB]; EA[i] = ep[i * NB];
    }
#pragma unroll
    for (int i = B1; i < 4 * B1; i++) {
        pfL2(pp + (size_t)i * NB); pfL2(tp + (size_t)i * NB); pfL2(ep + (size_t)i * NB);
    }

    for (int tb = 0; tb < NBT1; tb += 2) {
        // L2 prefetch: batches tb+2 and tb+3 (~2-3 batches of compute ahead of use)
        {
            const int f2 = (tb + 2 < NBT1) ? tb + 2 : NBT1 - 1;
            const int f3 = (tb + 3 < NBT1) ? tb + 3 : NBT1 - 1;
            const size_t b2 = (size_t)f2 * B1 * NB;
            const size_t b3 = (size_t)f3 * B1 * NB;
#pragma unroll
            for (int i = 0; i < B1; i++) {
                pfL2(pp + b2 + i * NB); pfL2(tp + b2 + i * NB); pfL2(ep + b2 + i * NB);
                pfL2(pp + b3 + i * NB); pfL2(tp + b3 + i * NB); pfL2(ep + b3 + i * NB);
            }
        }

        // register load: batch tb+1 (should be L2-resident from earlier prefetch)
        {
            const size_t base = (size_t)(tb + 1) * B1 * NB;
#pragma unroll
            for (int i = 0; i < B1; i++) {
                PB[i] = pp[base + i * NB]; TB[i] = tp[base + i * NB]; EB[i] = ep[base + i * NB];
            }
        }

        // chunk boundary: CLEN=32 steps = 4 batches -> tb % 4 == 0
        if ((tb & 3) == 0) {
            const int c = tb >> 2;
            g_ck_snow[c * NB + b] = snow;
            g_ck_soil[c * NB + b] = soil;
        }

#pragma unroll
        for (int i = 0; i < B1; i++)
            hydro_step(q, PA[i], TA[i], EA[i], snow, soil, fx);

        // register load: batch tb+2
        if (tb + 2 < NBT1) {
            const size_t base = (size_t)(tb + 2) * B1 * NB;
#pragma unroll
            for (int i = 0; i < B1; i++) {
                PA[i] = pp[base + i * NB]; TA[i] = tp[base + i * NB]; EA[i] = ep[base + i * NB];
            }
        }

#pragma unroll
        for (int i = 0; i < B1; i++)
            hydro_step(q, PB[i], TB[i], EB[i], snow, soil, fx);
    }

    // keep fx formally live (prevents any cross-pass DCE asymmetry games)
    if (b < 0) g_ck_soil[b & 1] = fx[0] + fx[1] + fx[2] + fx[3] + fx[4] + fx[5] + fx[6] + fx[7];
}

// ---------------- pass 2: parallel chunks from checkpoints, store fluxes ----
__global__ void __launch_bounds__(128)
hydro_pass2(const float* __restrict__ prcp,
            const float* __restrict__ temp,
            const float* __restrict__ pet,
            const float* __restrict__ sp,
            float* __restrict__ out)
{
    const int b = blockIdx.x * 128 + threadIdx.x;
    const int c = blockIdx.y;
    const Params q = load_params(sp, b);

    float snow = g_ck_snow[c * NB + b];
    float soil = g_ck_soil[c * NB + b];

    const size_t t0 = (size_t)c * CLEN;
    const float* pp = prcp + t0 * NB + b;
    const float* tp = temp + t0 * NB + b;
    const float* ep = pet  + t0 * NB + b;
    float*       o  = out  + t0 * (8 * NB) + b;

    float PA[B2], TA[B2], EA[B2];
    float PB[B2], TB[B2], EB[B2];
    float fx[8];

#pragma unroll
    for (int i = 0; i < B2; i++) {
        PA[i] = pp[i * NB]; TA[i] = tp[i * NB]; EA[i] = ep[i * NB];
    }

    for (int tb = 0; tb < NBT2; tb += 2) {
        {
            const size_t base = (size_t)(tb + 1) * B2 * NB;
#pragma unroll
            for (int i = 0; i < B2; i++) {
                PB[i] = pp[base + i * NB]; TB[i] = tp[base + i * NB]; EB[i] = ep[base + i * NB];
            }
        }
#pragma unroll
        for (int i = 0; i < B2; i++) {
            hydro_step(q, PA[i], TA[i], EA[i], snow, soil, fx);
            __stcs(o + 0 * NB, fx[0]); __stcs(o + 1 * NB, fx[1]);
            __stcs(o + 2 * NB, fx[2]); __stcs(o + 3 * NB, fx[3]);
            __stcs(o + 4 * NB, fx[4]); __stcs(o + 5 * NB, fx[5]);
            __stcs(o + 6 * NB, fx[6]); __stcs(o + 7 * NB, fx[7]);
            o += 8 * NB;
        }
        if (tb + 2 < NBT2) {
            const size_t base = (size_t)(tb + 2) * B2 * NB;
#pragma unroll
            for (int i = 0; i < B2; i++) {
                PA[i] = pp[base + i * NB]; TA[i] = tp[base + i * NB]; EA[i] = ep[base + i * NB];
            }
        }
#pragma unroll
        for (int i = 0; i < B2; i++) {
            hydro_step(q, PB[i], TB[i], EB[i], snow, soil, fx);
            __stcs(o + 0 * NB, fx[0]); __stcs(o + 1 * NB, fx[1]);
            __stcs(o + 2 * NB, fx[2]); __stcs(o + 3 * NB, fx[3]);
            __stcs(o + 4 * NB, fx[4]); __stcs(o + 5 * NB, fx[5]);
            __stcs(o + 6 * NB, fx[6]); __stcs(o + 7 * NB, fx[7]);
            o += 8 * NB;
        }
    }
}

extern "C" void kernel_launch(void* const* d_in, const int* in_sizes, int n_in,
                              void* d_out, int out_size)
{
    const float* prcp = (const float*)d_in[0];
    const float* temp = (const float*)d_in[1];
    const float* pet  = (const float*)d_in[2];
    const float* sp   = (const float*)d_in[3];
    float* out = (float*)d_out;

    // pass 1: 256 warps, serial scan, checkpoints every 32 steps
    hydro_pass1<<<NB / 32, 32>>>(prcp, temp, pet, sp);
    // pass 2: 32 chunks x 64 blocks x 128 threads = 8192 warps
    dim3 grid2(NB / 128, CHUNKS);
    hydro_pass2<<<grid2, 128>>>(prcp, temp, pet, sp, out);
}

// round 6
// speedup vs baseline: 2.9695x; 1.3813x over previous
#include <cuda_runtime.h>
#include <cstdint>

#define T_STEPS 1024
#define NB 8192
#define NP 6
#define CHUNKS 32
#define CLEN (T_STEPS / CHUNKS)      // 32 steps per chunk
#define B1 8                         // pass-1 batch (steps per pipeline stage)
#define NBT1 (T_STEPS / B1)          // 128 batches
#define STAGES 6                     // cp.async ring depth (144 outstanding copies)
#define B2 4                         // pass-2 register batch
#define NBT2 (CLEN / B2)             // 8 batches per chunk

// checkpoint scratch: state at the START of each chunk (2 MB -> L2 resident)
__device__ float g_ck_snow[CHUNKS * NB];
__device__ float g_ck_soil[CHUNKS * NB];

struct Params {
    float Qmax, Df, Tmax, Tmin, Smax, invSmax, posf_l2, c0;
};

__device__ __forceinline__ Params load_params(const float* __restrict__ sp, int b)
{
    const float lo[NP] = {0.0f, 100.0f, 10.0f, 0.0f, 0.0f, -3.0f};
    const float hi[NP] = {0.1f, 1500.0f, 50.0f, 5.0f, 3.0f, 0.0f};
    float prm[NP];
#pragma unroll
    for (int i = 0; i < NP; i++) {
        float x = sp[b * NP + i];
        float s = 1.0f / (1.0f + __expf(-x));
        prm[i] = lo[i] + (hi[i] - lo[i]) * s;
    }
    Params q;
    q.Smax = prm[1]; q.Qmax = prm[2]; q.Df = prm[3];
    q.Tmax = prm[4]; q.Tmin = prm[5];
    q.invSmax = 1.0f / prm[1];
    const float negf_l2 = -prm[0] * 1.4426950408889634f;   // -f*log2(e)
    q.posf_l2 = -negf_l2;
    q.c0 = negf_l2 * prm[1];                                // -f*log2(e)*Smax
    return q;
}

// one EXP-HYDRO step (MUST stay bit-identical between pass1 and pass2)
__device__ __forceinline__ void hydro_step(const Params& q,
                                           float p, float tm, float pe,
                                           float& snow, float& soil,
                                           float fx[8])
{
    const float snowfall    = (tm < q.Tmin) ? p : 0.0f;
    const float rainfall    = p - snowfall;
    const float melt        = fminf(snow, q.Df * fmaxf(tm - q.Tmax, 0.0f));
    const float evap        = pe * fminf(soil * q.invSmax, 1.0f);
    const float baseflow    = q.Qmax * exp2f(fminf(fmaf(q.posf_l2, soil, q.c0), 0.0f));
    const float surfaceflow = fmaxf(soil - q.Smax, 0.0f);

    const float d_snow = snowfall - melt;
    const float d_soil = rainfall + melt - evap - baseflow - surfaceflow;

    snow = fmaxf(snow + d_snow, 1e-6f);
    soil = fmaxf(soil + d_soil, 1e-6f);

    fx[0] = snowfall; fx[1] = rainfall; fx[2] = melt; fx[3] = evap;
    fx[4] = baseflow; fx[5] = surfaceflow; fx[6] = d_snow; fx[7] = d_soil;
}

__device__ __forceinline__ void cpasync4(unsigned int dst_smem, const float* src)
{
    asm volatile("cp.async.ca.shared.global [%0], [%1], 4;"
                 :: "r"(dst_smem), "l"(src));
}
__device__ __forceinline__ void cp_commit()
{
    asm volatile("cp.async.commit_group;" ::: "memory");
}
template <int N>
__device__ __forceinline__ void cp_wait()
{
    asm volatile("cp.async.wait_group %0;" :: "n"(N) : "memory");
}

// ---------------- pass 1: serial scan, cp.async smem ring pipeline ----------
__global__ void __launch_bounds__(32)
hydro_pass1(const float* __restrict__ prcp,
            const float* __restrict__ temp,
            const float* __restrict__ pet,
            const float* __restrict__ sp)
{
    __shared__ float ring[STAGES][3][B1][32];   // 18 KB

    const int lane = threadIdx.x;
    const int b = blockIdx.x * 32 + lane;
    const Params q = load_params(sp, b);

    const float* pp = prcp + b;
    const float* tp = temp + b;
    const float* ep = pet  + b;

    // issue one batch worth of cp.async into stage s (24 copies, one group)
    auto issue = [&](int batch, int s) {
        const int bc = (batch < NBT1) ? batch : NBT1 - 1;   // clamp tail (redundant, harmless)
        const size_t base = (size_t)bc * B1 * NB;
        unsigned int sm0 = (unsigned int)__cvta_generic_to_shared(&ring[s][0][0][lane]);
        unsigned int sm1 = (unsigned int)__cvta_generic_to_shared(&ring[s][1][0][lane]);
        unsigned int sm2 = (unsigned int)__cvta_generic_to_shared(&ring[s][2][0][lane]);
#pragma unroll
        for (int i = 0; i < B1; i++) {
            cpasync4(sm0 + i * 128, pp + base + i * NB);
            cpasync4(sm1 + i * 128, tp + base + i * NB);
            cpasync4(sm2 + i * 128, ep + base + i * NB);
        }
        cp_commit();
    };

    // prologue: fill STAGES-1 stages
#pragma unroll
    for (int s = 0; s < STAGES - 1; s++)
        issue(s, s);

    float snow = 0.0f, soil = 0.0f;
    float fx[8];

    for (int tb = 0; tb < NBT1; tb++) {
        // top off the ring: batch tb+STAGES-1 into the stage consumed last iter
        issue(tb + STAGES - 1, (tb + STAGES - 1) % STAGES);

        // wait until at most STAGES-1 groups pending => batch tb's group landed
        cp_wait<STAGES - 1>();
        __syncwarp();

        // chunk boundary: CLEN=32 steps = 4 batches
        if ((tb & 3) == 0) {
            const int c = tb >> 2;
            g_ck_snow[c * NB + b] = snow;
            g_ck_soil[c * NB + b] = soil;
        }

        const int s = tb % STAGES;
#pragma unroll
        for (int i = 0; i < B1; i++) {
            const float p  = ring[s][0][i][lane];
            const float tm = ring[s][1][i][lane];
            const float pe = ring[s][2][i][lane];
            hydro_step(q, p, tm, pe, snow, soil, fx);
        }
    }

    // keep fx formally live (prevent cross-pass DCE asymmetry)
    if (b < 0) g_ck_soil[b & 1] = fx[0] + fx[1] + fx[2] + fx[3] + fx[4] + fx[5] + fx[6] + fx[7];
}

// ---------------- pass 2: parallel chunks from checkpoints, store fluxes ----
__global__ void __launch_bounds__(128)
hydro_pass2(const float* __restrict__ prcp,
            const float* __restrict__ temp,
            const float* __restrict__ pet,
            const float* __restrict__ sp,
            float* __restrict__ out)
{
    const int b = blockIdx.x * 128 + threadIdx.x;
    const int c = blockIdx.y;
    const Params q = load_params(sp, b);

    float snow = g_ck_snow[c * NB + b];
    float soil = g_ck_soil[c * NB + b];

    const size_t t0 = (size_t)c * CLEN;
    const float* pp = prcp + t0 * NB + b;
    const float* tp = temp + t0 * NB + b;
    const float* ep = pet  + t0 * NB + b;
    float*       o  = out  + t0 * (8 * NB) + b;

    float PA[B2], TA[B2], EA[B2];
    float PB[B2], TB[B2], EB[B2];
    float fx[8];

#pragma unroll
    for (int i = 0; i < B2; i++) {
        PA[i] = pp[i * NB]; TA[i] = tp[i * NB]; EA[i] = ep[i * NB];
    }

    for (int tb = 0; tb < NBT2; tb += 2) {
        {
            const size_t base = (size_t)(tb + 1) * B2 * NB;
#pragma unroll
            for (int i = 0; i < B2; i++) {
                PB[i] = pp[base + i * NB]; TB[i] = tp[base + i * NB]; EB[i] = ep[base + i * NB];
            }
        }
#pragma unroll
        for (int i = 0; i < B2; i++) {
            hydro_step(q, PA[i], TA[i], EA[i], snow, soil, fx);
            __stcs(o + 0 * NB, fx[0]); __stcs(o + 1 * NB, fx[1]);
            __stcs(o + 2 * NB, fx[2]); __stcs(o + 3 * NB, fx[3]);
            __stcs(o + 4 * NB, fx[4]); __stcs(o + 5 * NB, fx[5]);
            __stcs(o + 6 * NB, fx[6]); __stcs(o + 7 * NB, fx[7]);
            o += 8 * NB;
        }
        if (tb + 2 < NBT2) {
            const size_t base = (size_t)(tb + 2) * B2 * NB;
#pragma unroll
            for (int i = 0; i < B2; i++) {
                PA[i] = pp[base + i * NB]; TA[i] = tp[base + i * NB]; EA[i] = ep[base + i * NB];
            }
        }
#pragma unroll
        for (int i = 0; i < B2; i++) {
            hydro_step(q, PB[i], TB[i], EB[i], snow, soil, fx);
            __stcs(o + 0 * NB, fx[0]); __stcs(o + 1 * NB, fx[1]);
            __stcs(o + 2 * NB, fx[2]); __stcs(o + 3 * NB, fx[3]);
            __stcs(o + 4 * NB, fx[4]); __stcs(o + 5 * NB, fx[5]);
            __stcs(o + 6 * NB, fx[6]); __stcs(o + 7 * NB, fx[7]);
            o += 8 * NB;
        }
    }
}

extern "C" void kernel_launch(void* const* d_in, const int* in_sizes, int n_in,
                              void* d_out, int out_size)
{
    const float* prcp = (const float*)d_in[0];
    const float* temp = (const float*)d_in[1];
    const float* pet  = (const float*)d_in[2];
    const float* sp   = (const float*)d_in[3];
    float* out = (float*)d_out;

    // pass 1: 256 warps, serial scan, cp.async-pipelined forcing loads
    hydro_pass1<<<NB / 32, 32>>>(prcp, temp, pet, sp);
    // pass 2: 32 chunks x 64 blocks x 128 threads = 8192 warps
    dim3 grid2(NB / 128, CHUNKS);
    hydro_pass2<<<grid2, 128>>>(prcp, temp, pet, sp, out);
}

// round 7
// speedup vs baseline: 3.2497x; 1.0944x over previous
#include <cuda_runtime.h>
#include <cstdint>

#define T_STEPS 1024
#define NB 8192
#define NP 6
#define CHUNKS 32
#define CLEN (T_STEPS / CHUNKS)      // 32 steps per chunk
#define B1 8                         // scan batch (steps per pipeline stage)
#define NBT1 (T_STEPS / B1)          // 128 batches
#define STAGES 4                     // cp.async ring depth per warp
#define B2 4                         // consumer register batch
#define NBT2 (CLEN / B2)             // 8 batches per chunk
#define SCAN_BLOCKS 64               // 64 blocks x 128 thr = 8192 scan threads
#define P2_PER_CHUNK 64              // 8192 basins / 128 thr
#define TOTAL_BLOCKS (SCAN_BLOCKS + CHUNKS * P2_PER_CHUNK)   // 2112

// checkpoint scratch + per-chunk ready counters
__device__ float g_ck_snow[CHUNKS * NB];
__device__ float g_ck_soil[CHUNKS * NB];
__device__ int   g_cnt[CHUNKS];

struct Params {
    float Qmax, Df, Tmax, Tmin, Smax, invSmax, posf_l2, c0;
};

__device__ __forceinline__ Params load_params(const float* __restrict__ sp, int b)
{
    const float lo[NP] = {0.0f, 100.0f, 10.0f, 0.0f, 0.0f, -3.0f};
    const float hi[NP] = {0.1f, 1500.0f, 50.0f, 5.0f, 3.0f, 0.0f};
    float prm[NP];
#pragma unroll
    for (int i = 0; i < NP; i++) {
        float x = sp[b * NP + i];
        float s = 1.0f / (1.0f + __expf(-x));
        prm[i] = lo[i] + (hi[i] - lo[i]) * s;
    }
    Params q;
    q.Smax = prm[1]; q.Qmax = prm[2]; q.Df = prm[3];
    q.Tmax = prm[4]; q.Tmin = prm[5];
    q.invSmax = 1.0f / prm[1];
    const float negf_l2 = -prm[0] * 1.4426950408889634f;   // -f*log2(e)
    q.posf_l2 = -negf_l2;
    q.c0 = negf_l2 * prm[1];                                // -f*log2(e)*Smax
    return q;
}

// one EXP-HYDRO step (MUST stay bit-identical between producer and consumer)
__device__ __forceinline__ void hydro_step(const Params& q,
                                           float p, float tm, float pe,
                                           float& snow, float& soil,
                                           float fx[8])
{
    const float snowfall    = (tm < q.Tmin) ? p : 0.0f;
    const float rainfall    = p - snowfall;
    const float melt        = fminf(snow, q.Df * fmaxf(tm - q.Tmax, 0.0f));
    const float evap        = pe * fminf(soil * q.invSmax, 1.0f);
    const float baseflow    = q.Qmax * exp2f(fminf(fmaf(q.posf_l2, soil, q.c0), 0.0f));
    const float surfaceflow = fmaxf(soil - q.Smax, 0.0f);

    const float d_snow = snowfall - melt;
    const float d_soil = rainfall + melt - evap - baseflow - surfaceflow;

    snow = fmaxf(snow + d_snow, 1e-6f);
    soil = fmaxf(soil + d_soil, 1e-6f);

    fx[0] = snowfall; fx[1] = rainfall; fx[2] = melt; fx[3] = evap;
    fx[4] = baseflow; fx[5] = surfaceflow; fx[6] = d_snow; fx[7] = d_soil;
}

__device__ __forceinline__ void cpasync4(unsigned int dst_smem, const float* src)
{
    asm volatile("cp.async.ca.shared.global [%0], [%1], 4;"
                 :: "r"(dst_smem), "l"(src));
}
__device__ __forceinline__ void cp_commit()
{
    asm volatile("cp.async.commit_group;" ::: "memory");
}
template <int N>
__device__ __forceinline__ void cp_wait()
{
    asm volatile("cp.async.wait_group %0;" :: "n"(N) : "memory");
}
__device__ __forceinline__ int ld_acq(const int* p)
{
    int v;
    asm volatile("ld.acquire.gpu.global.s32 %0, [%1];" : "=r"(v) : "l"(p) : "memory");
    return v;
}

__global__ void zero_cnt_kernel()
{
    if (threadIdx.x < CHUNKS) g_cnt[threadIdx.x] = 0;
}

// ---------------- fused: scan producers (bids 0..63) + flux consumers -------
__global__ void __launch_bounds__(128)
hydro_fused(const float* __restrict__ prcp,
            const float* __restrict__ temp,
            const float* __restrict__ pet,
            const float* __restrict__ sp,
            float* __restrict__ out)
{
    // per-warp cp.async ring: 4 warps x 4 stages x 3 arrays x 8 steps x 32 lanes
    __shared__ float ring[4][STAGES][3][B1][32];   // 48 KB exactly

    const int bid = blockIdx.x;
    const int tid = threadIdx.x;

    if (bid < SCAN_BLOCKS) {
        // ================= producer: serial state scan =================
        const int w    = tid >> 5;
        const int lane = tid & 31;
        const int b    = bid * 128 + tid;
        const Params q = load_params(sp, b);

        const float* pp = prcp + b;
        const float* tp = temp + b;
        const float* ep = pet  + b;

        auto issue = [&](int batch, int s) {
            const int bc = (batch < NBT1) ? batch : NBT1 - 1;
            const size_t base = (size_t)bc * B1 * NB;
            unsigned int sm0 = (unsigned int)__cvta_generic_to_shared(&ring[w][s][0][0][lane]);
            unsigned int sm1 = (unsigned int)__cvta_generic_to_shared(&ring[w][s][1][0][lane]);
            unsigned int sm2 = (unsigned int)__cvta_generic_to_shared(&ring[w][s][2][0][lane]);
#pragma unroll
            for (int i = 0; i < B1; i++) {
                cpasync4(sm0 + i * 128, pp + base + i * NB);
                cpasync4(sm1 + i * 128, tp + base + i * NB);
                cpasync4(sm2 + i * 128, ep + base + i * NB);
            }
            cp_commit();
        };

#pragma unroll
        for (int s = 0; s < STAGES - 1; s++)
            issue(s, s);

        float snow = 0.0f, soil = 0.0f;
        float fx[8];

        for (int tb = 0; tb < NBT1; tb++) {
            issue(tb + STAGES - 1, (tb + STAGES - 1) % STAGES);
            cp_wait<STAGES - 1>();
            __syncwarp();

            if ((tb & 3) == 0) {
                const int c = tb >> 2;
                g_ck_snow[c * NB + b] = snow;
                g_ck_soil[c * NB + b] = soil;
                __threadfence();          // make checkpoint visible device-wide
                __syncwarp();             // all lanes' fences done before flag
                if (lane == 0) atomicAdd(&g_cnt[c], 1);
                if (c == CHUNKS - 1) {
                    // last checkpoint published: remaining state evolution is dead work
                    cp_wait<0>();
                    if (b < 0) g_ck_soil[b & 1] = fx[0] + fx[1] + fx[2] + fx[3]
                                                + fx[4] + fx[5] + fx[6] + fx[7];
                    return;
                }
            }

            const int s = tb % STAGES;
#pragma unroll
            for (int i = 0; i < B1; i++) {
                const float p  = ring[w][s][0][i][lane];
                const float tm = ring[w][s][1][i][lane];
                const float pe = ring[w][s][2][i][lane];
                hydro_step(q, p, tm, pe, snow, soil, fx);
            }
        }
        if (b < 0) g_ck_soil[b & 1] = fx[0] + fx[1] + fx[2] + fx[3]
                                    + fx[4] + fx[5] + fx[6] + fx[7];
    } else {
        // ================= consumer: recompute chunk, store fluxes =====
        const int idx = bid - SCAN_BLOCKS;
        const int c   = idx >> 6;            // chunk-major: early chunks first
        const int b   = (idx & 63) * 128 + tid;
        const Params q = load_params(sp, b);

        // wait until all 256 scan warps published checkpoint c
        if (tid == 0) {
            while (ld_acq(&g_cnt[c]) < 256)
                __nanosleep(256);
        }
        __syncthreads();

        float snow = g_ck_snow[c * NB + b];
        float soil = g_ck_soil[c * NB + b];

        const size_t t0 = (size_t)c * CLEN;
        const float* pp = prcp + t0 * NB + b;
        const float* tp = temp + t0 * NB + b;
        const float* ep = pet  + t0 * NB + b;
        float*       o  = out  + t0 * (8 * NB) + b;

        float PA[B2], TA[B2], EA[B2];
        float PB[B2], TB[B2], EB[B2];
        float fx[8];

#pragma unroll
        for (int i = 0; i < B2; i++) {
            PA[i] = pp[i * NB]; TA[i] = tp[i * NB]; EA[i] = ep[i * NB];
        }

        for (int tb = 0; tb < NBT2; tb += 2) {
            {
                const size_t base = (size_t)(tb + 1) * B2 * NB;
#pragma unroll
                for (int i = 0; i < B2; i++) {
                    PB[i] = pp[base + i * NB]; TB[i] = tp[base + i * NB]; EB[i] = ep[base + i * NB];
                }
            }
#pragma unroll
            for (int i = 0; i < B2; i++) {
                hydro_step(q, PA[i], TA[i], EA[i], snow, soil, fx);
                __stcs(o + 0 * NB, fx[0]); __stcs(o + 1 * NB, fx[1]);
                __stcs(o + 2 * NB, fx[2]); __stcs(o + 3 * NB, fx[3]);
                __stcs(o + 4 * NB, fx[4]); __stcs(o + 5 * NB, fx[5]);
                __stcs(o + 6 * NB, fx[6]); __stcs(o + 7 * NB, fx[7]);
                o += 8 * NB;
            }
            if (tb + 2 < NBT2) {
                const size_t base = (size_t)(tb + 2) * B2 * NB;
#pragma unroll
                for (int i = 0; i < B2; i++) {
                    PA[i] = pp[base + i * NB]; TA[i] = tp[base + i * NB]; EA[i] = ep[base + i * NB];
                }
            }
#pragma unroll
            for (int i = 0; i < B2; i++) {
                hydro_step(q, PB[i], TB[i], EB[i], snow, soil, fx);
                __stcs(o + 0 * NB, fx[0]); __stcs(o + 1 * NB, fx[1]);
                __stcs(o + 2 * NB, fx[2]); __stcs(o + 3 * NB, fx[3]);
                __stcs(o + 4 * NB, fx[4]); __stcs(o + 5 * NB, fx[5]);
                __stcs(o + 6 * NB, fx[6]); __stcs(o + 7 * NB, fx[7]);
                o += 8 * NB;
            }
        }
    }
}

extern "C" void kernel_launch(void* const* d_in, const int* in_sizes, int n_in,
                              void* d_out, int out_size)
{
    const float* prcp = (const float*)d_in[0];
    const float* temp = (const float*)d_in[1];
    const float* pet  = (const float*)d_in[2];
    const float* sp   = (const float*)d_in[3];
    float* out = (float*)d_out;

    zero_cnt_kernel<<<1, 32>>>();
    hydro_fused<<<TOTAL_BLOCKS, 128>>>(prcp, temp, pet, sp, out);
}